// round 12
// baseline (speedup 1.0000x reference)
#include <cuda_runtime.h>
#include <cuda_fp16.h>
#include <stdint.h>

// SNU on GB300 (base sm_103 ISA — mma.sync HMMA path):
//   out[b,h,t] = spike recurrence over xw[t,b,h] = sum_i x[b,i,t]*W[i,h]
//   B=128, I=512, H=512, T=512, DECAY=0.8
//
// v6 structure:
//  - reset_flags: zero per-batch completion counters (graph-replay safe)
//  - convert_w:   W -> fp16 split pair (b0,b1) [h][i]
//  - fused:       grid = 4096 GEMM CTAs + 512 recur CTAs (scheduled last).
//                 GEMM CTAs (round-11 proven: fused A-convert, 3 split
//                 products, CTA 128m x 64n, 4-stage cp.async) signal per-batch
//                 flags; recur CTAs spin until their batch's 32 producers
//                 finish, then run the proven v2 staged recurrence — the
//                 recur tail hides inside the GEMM's drain waves.

typedef unsigned long long ull;

__device__ float  g_xw[33554432];               // 65536 x 512 fp32
__device__ __half g_b0[262144], g_b1[262144];   // 512 x 512 fp16 splits of W^T
__device__ int    g_bflag[128];                 // per-batch producer counters

// ---------------------------------------------------------------- helpers ---
__device__ __forceinline__ uint32_t smem_u32(const void* p) {
    uint32_t a;
    asm("{ .reg .u64 t; cvta.to.shared.u64 t, %1; cvt.u32.u64 %0, t; }"
        : "=r"(a) : "l"(p));
    return a;
}
__device__ __forceinline__ void cp16(uint32_t dst, const void* src) {
    asm volatile("cp.async.cg.shared.global [%0], [%1], 16;"
                 :: "r"(dst), "l"(src) : "memory");
}
__device__ __forceinline__ void ldsm4(uint32_t a, uint32_t& r0, uint32_t& r1,
                                      uint32_t& r2, uint32_t& r3) {
    asm volatile("ldmatrix.sync.aligned.m8n8.x4.shared.b16 {%0,%1,%2,%3}, [%4];"
                 : "=r"(r0), "=r"(r1), "=r"(r2), "=r"(r3) : "r"(a));
}
__device__ __forceinline__ void mma16816(float* d, const uint32_t* a,
                                         uint32_t b0, uint32_t b1) {
    asm volatile(
        "mma.sync.aligned.m16n8k16.row.col.f32.f16.f16.f32 "
        "{%0,%1,%2,%3}, {%4,%5,%6,%7}, {%8,%9}, {%0,%1,%2,%3};"
        : "+f"(d[0]), "+f"(d[1]), "+f"(d[2]), "+f"(d[3])
        : "r"(a[0]), "r"(a[1]), "r"(a[2]), "r"(a[3]), "r"(b0), "r"(b1));
}
__device__ __forceinline__ void split_pair(float ve, float vo,
                                           uint32_t& r0, uint32_t& r1) {
    __half2 h = __floats2half2_rn(ve, vo);
    float2  w = __half22float2(h);
    __half2 g = __floats2half2_rn(ve - w.x, vo - w.y);
    r0 = *(uint32_t*)&h;
    r1 = *(uint32_t*)&g;
}

// ---------------------------------------------------------------- reset ---
__global__ void reset_flags() {
    if (threadIdx.x < 128) g_bflag[threadIdx.x] = 0;
}

// ------------------------------------------------------------ convert_w ---
__global__ __launch_bounds__(256) void convert_w_kernel(const float* __restrict__ W) {
    __shared__ float tile[64][65];
    int r0 = blockIdx.y * 64, c0 = blockIdx.x * 64;
    const float* sp = W + (size_t)r0 * 512 + c0;
    for (int e = threadIdx.x; e < 1024; e += 256) {
        int r = e >> 4, c = (e & 15) << 2;
        float4 v = *(const float4*)(sp + (size_t)r * 512 + c);
        tile[r][c] = v.x; tile[r][c + 1] = v.y;
        tile[r][c + 2] = v.z; tile[r][c + 3] = v.w;
    }
    __syncthreads();
    size_t ob = (size_t)c0 * 512 + r0;
    for (int e = threadIdx.x; e < 1024; e += 256) {
        int r = e >> 4, c = (e & 15) << 2;
        union { __half h[4]; ull u; } p0, p1;
        #pragma unroll
        for (int q = 0; q < 4; q++) {
            float v = tile[c + q][r];
            __half h0 = __float2half_rn(v);
            float rr = v - __half2float(h0);
            p0.h[q] = h0; p1.h[q] = __float2half_rn(rr);
        }
        size_t o = ob + (size_t)r * 512 + c;
        *(ull*)(g_b0 + o) = p0.u;
        *(ull*)(g_b1 + o) = p1.u;
    }
}

// --------------------------------------------- fused GEMM + overlapped recur ---
#define STG    27136
#define XPITCH 132
#define NGEMM  4096

__global__ __launch_bounds__(256, 2) void fused_kernel(
    const float* __restrict__ x, const float* __restrict__ bias,
    float* __restrict__ out)
{
    extern __shared__ char smraw[];
    const uint32_t smb = smem_u32(smraw);
    const int tid = threadIdx.x;

    if (blockIdx.x < NGEMM) {
        // ======================= GEMM CTA (round-11 proven body) ==========
        const int gid  = blockIdx.x;
        const int n0   = (gid & 7) * 64;
        const int mt   = gid >> 3;                 // m-tile 0..511
        const int b    = mt >> 2;
        const int t0   = (mt & 3) * 128;
        const int wid  = tid >> 5, lane = tid & 31;
        const int mw   = (wid >> 1) * 32;
        const int nw   = (wid & 1) * 32;

        const float* xb = x + (size_t)b * 262144 + t0;

        float acc[2][4][4];
        #pragma unroll
        for (int i = 0; i < 2; i++)
            #pragma unroll
            for (int j = 0; j < 4; j++)
                #pragma unroll
                for (int q = 0; q < 4; q++) acc[i][j][q] = 0.0f;

        #define LOAD_CHUNK(c, slot) do {                                      \
            int _k0 = (c) << 5;                                               \
            uint32_t _sb = smb + (slot) * STG;                                \
            _Pragma("unroll")                                                 \
            for (int _q = 0; _q < 4; _q++) {                                  \
                int _e = tid + 256 * _q;                                      \
                int _r = _e >> 5, _c = _e & 31;                               \
                cp16(_sb + _r * (XPITCH * 4) + _c * 16,                       \
                     xb + (size_t)(_k0 + _r) * 512 + _c * 4);                 \
            }                                                                 \
            {                                                                 \
                int _r = tid >> 2, _c4 = tid & 3;                             \
                cp16(_sb + 16896 + _r * 80 + _c4 * 16,                        \
                     g_b0 + (size_t)(n0 + _r) * 512 + _k0 + _c4 * 8);         \
                cp16(_sb + 22016 + _r * 80 + _c4 * 16,                        \
                     g_b1 + (size_t)(n0 + _r) * 512 + _k0 + _c4 * 8);         \
            }                                                                 \
        } while (0)

        LOAD_CHUNK(0, 0); asm volatile("cp.async.commit_group;" ::: "memory");
        LOAD_CHUNK(1, 1); asm volatile("cp.async.commit_group;" ::: "memory");
        LOAD_CHUNK(2, 2); asm volatile("cp.async.commit_group;" ::: "memory");

        for (int i = 0; i < 16; i++) {
            asm volatile("cp.async.wait_group 2;" ::: "memory");
            __syncthreads();
            if (i + 3 < 16) LOAD_CHUNK(i + 3, (i + 3) & 3);
            asm volatile("cp.async.commit_group;" ::: "memory");

            const int slot = i & 3;
            const float* Xs = (const float*)(smraw + slot * STG);
            const uint32_t bbase = smb + slot * STG + 16896;

            uint32_t ar0[2][2][4], ar1[2][2][4];
            #pragma unroll
            for (int mi = 0; mi < 2; mi++) {
                #pragma unroll
                for (int ks = 0; ks < 2; ks++) {
                    const int tq = mw + mi * 16 + (lane >> 2);
                    const int kq = ks * 16 + (lane & 3) * 2;
                    const float* p = Xs + kq * XPITCH + tq;
                    split_pair(p[0],              p[XPITCH],
                               ar0[mi][ks][0], ar1[mi][ks][0]);
                    split_pair(p[8],              p[XPITCH + 8],
                               ar0[mi][ks][1], ar1[mi][ks][1]);
                    split_pair(p[8 * XPITCH],     p[9 * XPITCH],
                               ar0[mi][ks][2], ar1[mi][ks][2]);
                    split_pair(p[8 * XPITCH + 8], p[9 * XPITCH + 8],
                               ar0[mi][ks][3], ar1[mi][ks][3]);
                }
            }

            #pragma unroll
            for (int ks = 0; ks < 2; ks++) {
                const int col = ks * 16 + (lane >> 4) * 8;
                uint32_t br0[2][4], br1[2][4];
                #pragma unroll
                for (int nb = 0; nb < 2; nb++) {
                    int row = nw + nb * 16 + (lane & 15);
                    ldsm4(bbase + (row * 40 + col) * 2,
                          br0[nb][0], br0[nb][1], br0[nb][2], br0[nb][3]);
                    ldsm4(bbase + 5120 + (row * 40 + col) * 2,
                          br1[nb][0], br1[nb][1], br1[nb][2], br1[nb][3]);
                }
                #pragma unroll
                for (int mi = 0; mi < 2; mi++)
                    #pragma unroll
                    for (int nf = 0; nf < 4; nf++) {
                        int nb = nf >> 1, hh = nf & 1;
                        mma16816(acc[mi][nf], ar0[mi][ks], br0[nb][hh], br0[nb][hh + 2]);
                        mma16816(acc[mi][nf], ar0[mi][ks], br1[nb][hh], br1[nb][hh + 2]);
                        mma16816(acc[mi][nf], ar1[mi][ks], br0[nb][hh], br0[nb][hh + 2]);
                    }
            }
        }

        #pragma unroll
        for (int mi = 0; mi < 2; mi++) {
            int row = mt * 128 + mw + mi * 16 + (lane >> 2);
            #pragma unroll
            for (int nf = 0; nf < 4; nf++) {
                int col = n0 + nw + nf * 8 + ((lane & 3) << 1);
                *(float2*)(g_xw + (size_t)row * 512 + col) =
                    make_float2(acc[mi][nf][0], acc[mi][nf][1]);
                *(float2*)(g_xw + (size_t)(row + 8) * 512 + col) =
                    make_float2(acc[mi][nf][2], acc[mi][nf][3]);
            }
        }

        // signal: this CTA's slice of batch b is in g_xw
        __threadfence();
        __syncthreads();
        if (tid == 0) atomicAdd(&g_bflag[b], 1);

    } else {
        // ======================= recur CTA (v2, 256-thread variant) =======
        const int rid = blockIdx.x - NGEMM;       // 0..511
        const int b   = rid >> 2;
        const int h0  = (rid & 3) * 128;

        // wait for all 32 producer CTAs of batch b
        if (tid == 0) {
            while (atomicAdd(&g_bflag[b], 0) < 32) __nanosleep(200);
        }
        __syncthreads();
        __threadfence();

        float* smin = (float*)smraw;                          // [2][32*128]
        float (*buf)[33] = (float(*)[33])(smraw + 32768);     // [128][33]

        float bb = 0.0f, hs = 0.0f, y = 0.0f;
        if (tid < 128) bb = bias[h0 + tid];

        const float* gx = g_xw + ((size_t)b * 512) * 512 + h0;
        float*       po = out + ((size_t)b * 512 + h0) * 512;

        const uint32_t smin_u = smem_u32(smin);
        const int lrow = tid >> 3;            // 0..31 (t within chunk)
        const int lq   = (tid & 7) * 16;      // 16-float slice of 128-h row

        #define RLOAD(tc0, bsel) do {                                         \
            const float* _src = gx + (size_t)((tc0) + lrow) * 512 + lq;       \
            uint32_t _dst = smin_u + (((bsel) * 4096 + lrow * 128 + lq) * 4); \
            cp16(_dst,      _src);      cp16(_dst + 16, _src + 4);            \
            cp16(_dst + 32, _src + 8);  cp16(_dst + 48, _src + 12);           \
        } while (0)

        RLOAD(0, 0);
        asm volatile("cp.async.commit_group;" ::: "memory");

        for (int tc = 0; tc < 16; tc++) {
            if (tc < 15) {
                RLOAD((tc + 1) * 32, (tc + 1) & 1);
                asm volatile("cp.async.commit_group;" ::: "memory");
                asm volatile("cp.async.wait_group 1;" ::: "memory");
            } else {
                asm volatile("cp.async.wait_group 0;" ::: "memory");
            }
            __syncthreads();

            const float* cs = smin + (tc & 1) * 4096;
            if (tid < 128) {
                #pragma unroll
                for (int j = 0; j < 32; j++) {
                    float v = cs[j * 128 + tid];
                    hs = fmaxf(v + 0.8f * hs * (1.0f - y), 0.0f);
                    y  = (hs + bb > 0.0f) ? 1.0f : 0.0f;
                    buf[tid][j] = y;
                }
            }
            __syncthreads();
            const int r = tid >> 5;           // 0..7
            const int c = tid & 31;
            #pragma unroll
            for (int rr = 0; rr < 128; rr += 8)
                po[(size_t)(rr + r) * 512 + tc * 32 + c] = buf[rr + r][c];
            __syncthreads();
        }
    }
}

// ------------------------------------------------------------------- launch ---
extern "C" void kernel_launch(void* const* d_in, const int* in_sizes, int n_in,
                              void* d_out, int out_size)
{
    const float* x = (const float*)d_in[0];   // (128, 512, 512)
    const float* W = (const float*)d_in[1];   // (512, 512)
    const float* b = (const float*)d_in[2];   // (1, 512)
    float* out = (float*)d_out;               // (128, 512, 512) float32

    cudaFuncSetAttribute(fused_kernel,
                         cudaFuncAttributeMaxDynamicSharedMemorySize, 4 * STG);

    reset_flags<<<1, 128>>>();
    convert_w_kernel<<<dim3(8, 8), 256>>>(W);
    fused_kernel<<<NGEMM + 512, 256, 4 * STG>>>(x, b, out);
}

// round 13
// speedup vs baseline: 1.0338x; 1.0338x over previous
#include <cuda_runtime.h>
#include <cuda_fp16.h>
#include <stdint.h>

// SNU on GB300 (base sm_103 ISA — mma.sync HMMA path):
//   out[b,h,t] = spike recurrence over xw[t,b,h] = sum_i x[b,i,t]*W[i,h]
//   B=128, I=512, H=512, T=512, DECAY=0.8
//
// v7 structure (round-11 3-kernel layout):
//  - convert_w: W -> fp16 split pair (b0,b1) [h][i]
//  - gemm_fc:   fused A-convert GEMM. Main product a0b0 -> fp32 HMMA acc;
//               correction products a0b1 + a1b0 -> fp16-accumulator HMMA
//               (2x rate hypothesis on the legacy pipe), added in epilogue.
//  - recur v2:  2-buffer cp.async staged spike recurrence (62us proven)

typedef unsigned long long ull;

__device__ float  g_xw[33554432];               // 65536 x 512 fp32
__device__ __half g_b0[262144], g_b1[262144];   // 512 x 512 fp16 splits of W^T

// ---------------------------------------------------------------- helpers ---
__device__ __forceinline__ uint32_t smem_u32(const void* p) {
    uint32_t a;
    asm("{ .reg .u64 t; cvta.to.shared.u64 t, %1; cvt.u32.u64 %0, t; }"
        : "=r"(a) : "l"(p));
    return a;
}
__device__ __forceinline__ void cp16(uint32_t dst, const void* src) {
    asm volatile("cp.async.cg.shared.global [%0], [%1], 16;"
                 :: "r"(dst), "l"(src) : "memory");
}
__device__ __forceinline__ void ldsm4(uint32_t a, uint32_t& r0, uint32_t& r1,
                                      uint32_t& r2, uint32_t& r3) {
    asm volatile("ldmatrix.sync.aligned.m8n8.x4.shared.b16 {%0,%1,%2,%3}, [%4];"
                 : "=r"(r0), "=r"(r1), "=r"(r2), "=r"(r3) : "r"(a));
}
__device__ __forceinline__ void mma16816(float* d, const uint32_t* a,
                                         uint32_t b0, uint32_t b1) {
    asm volatile(
        "mma.sync.aligned.m16n8k16.row.col.f32.f16.f16.f32 "
        "{%0,%1,%2,%3}, {%4,%5,%6,%7}, {%8,%9}, {%0,%1,%2,%3};"
        : "+f"(d[0]), "+f"(d[1]), "+f"(d[2]), "+f"(d[3])
        : "r"(a[0]), "r"(a[1]), "r"(a[2]), "r"(a[3]), "r"(b0), "r"(b1));
}
// fp16-accumulator variant: D/C are 2 f16x2 regs
__device__ __forceinline__ void mma16816h(uint32_t* d, const uint32_t* a,
                                          uint32_t b0, uint32_t b1) {
    asm volatile(
        "mma.sync.aligned.m16n8k16.row.col.f16.f16.f16.f16 "
        "{%0,%1}, {%2,%3,%4,%5}, {%6,%7}, {%0,%1};"
        : "+r"(d[0]), "+r"(d[1])
        : "r"(a[0]), "r"(a[1]), "r"(a[2]), "r"(a[3]), "r"(b0), "r"(b1));
}
__device__ __forceinline__ void split_pair(float ve, float vo,
                                           uint32_t& r0, uint32_t& r1) {
    __half2 h = __floats2half2_rn(ve, vo);
    float2  w = __half22float2(h);
    __half2 g = __floats2half2_rn(ve - w.x, vo - w.y);
    r0 = *(uint32_t*)&h;
    r1 = *(uint32_t*)&g;
}

// ------------------------------------------------------------ convert_w ---
__global__ __launch_bounds__(256) void convert_w_kernel(const float* __restrict__ W) {
    __shared__ float tile[64][65];
    int r0 = blockIdx.y * 64, c0 = blockIdx.x * 64;
    const float* sp = W + (size_t)r0 * 512 + c0;
    for (int e = threadIdx.x; e < 1024; e += 256) {
        int r = e >> 4, c = (e & 15) << 2;
        float4 v = *(const float4*)(sp + (size_t)r * 512 + c);
        tile[r][c] = v.x; tile[r][c + 1] = v.y;
        tile[r][c + 2] = v.z; tile[r][c + 3] = v.w;
    }
    __syncthreads();
    size_t ob = (size_t)c0 * 512 + r0;
    for (int e = threadIdx.x; e < 1024; e += 256) {
        int r = e >> 4, c = (e & 15) << 2;
        union { __half h[4]; ull u; } p0, p1;
        #pragma unroll
        for (int q = 0; q < 4; q++) {
            float v = tile[c + q][r];
            __half h0 = __float2half_rn(v);
            float rr = v - __half2float(h0);
            p0.h[q] = h0; p1.h[q] = __float2half_rn(rr);
        }
        size_t o = ob + (size_t)r * 512 + c;
        *(ull*)(g_b0 + o) = p0.u;
        *(ull*)(g_b1 + o) = p1.u;
    }
}

// ------------------------------------------------ GEMM w/ fused A-convert ---
// CTA 128(M) x 64(N) x 32(K-chunk), 256 thr = 8 warps (4m x 2n), warp 32x32.
// Stage (27136 B): X fp32 32x132 pitch (16896) + b0 64x40h (5120) + b1 (5120).
// 4 stages = 108544 B.  16 k-chunks.
// Main product fp32-acc; corrections fp16-acc (rate experiment).

#define STG    27136
#define XPITCH 132

__global__ __launch_bounds__(256, 2) void gemm_fc(const float* __restrict__ x) {
    extern __shared__ char smraw[];
    const uint32_t smb = smem_u32(smraw);

    const int tid  = threadIdx.x;
    const int n0   = blockIdx.x * 64;
    const int mt   = blockIdx.y;                 // m-tile 0..511
    const int b    = mt >> 2;
    const int t0   = (mt & 3) * 128;
    const int wid  = tid >> 5, lane = tid & 31;
    const int mw   = (wid >> 1) * 32;
    const int nw   = (wid & 1) * 32;

    const float* xb = x + (size_t)b * 262144 + t0;   // + k*512 + t

    float acc[2][4][4];
    uint32_t accc[2][4][2];
    #pragma unroll
    for (int i = 0; i < 2; i++)
        #pragma unroll
        for (int j = 0; j < 4; j++) {
            #pragma unroll
            for (int q = 0; q < 4; q++) acc[i][j][q] = 0.0f;
            accc[i][j][0] = 0u; accc[i][j][1] = 0u;
        }

    #define LOAD_CHUNK(c, slot) do {                                          \
        int _k0 = (c) << 5;                                                   \
        uint32_t _sb = smb + (slot) * STG;                                    \
        _Pragma("unroll")                                                     \
        for (int _q = 0; _q < 4; _q++) {                                      \
            int _e = tid + 256 * _q;                                          \
            int _r = _e >> 5, _c = _e & 31;                                   \
            cp16(_sb + _r * (XPITCH * 4) + _c * 16,                           \
                 xb + (size_t)(_k0 + _r) * 512 + _c * 4);                     \
        }                                                                     \
        {                                                                     \
            int _r = tid >> 2, _c4 = tid & 3;                                 \
            cp16(_sb + 16896 + _r * 80 + _c4 * 16,                            \
                 g_b0 + (size_t)(n0 + _r) * 512 + _k0 + _c4 * 8);             \
            cp16(_sb + 22016 + _r * 80 + _c4 * 16,                            \
                 g_b1 + (size_t)(n0 + _r) * 512 + _k0 + _c4 * 8);             \
        }                                                                     \
    } while (0)

    LOAD_CHUNK(0, 0); asm volatile("cp.async.commit_group;" ::: "memory");
    LOAD_CHUNK(1, 1); asm volatile("cp.async.commit_group;" ::: "memory");
    LOAD_CHUNK(2, 2); asm volatile("cp.async.commit_group;" ::: "memory");

    for (int i = 0; i < 16; i++) {
        asm volatile("cp.async.wait_group 2;" ::: "memory");
        __syncthreads();
        if (i + 3 < 16) LOAD_CHUNK(i + 3, (i + 3) & 3);
        asm volatile("cp.async.commit_group;" ::: "memory");

        const int slot = i & 3;
        const float* Xs = (const float*)(smraw + slot * STG);
        const uint32_t bbase = smb + slot * STG + 16896;

        // ---- build A fragments (a0 + a1 splits) ----
        uint32_t ar0[2][2][4], ar1[2][2][4];
        #pragma unroll
        for (int mi = 0; mi < 2; mi++) {
            #pragma unroll
            for (int ks = 0; ks < 2; ks++) {
                const int tq = mw + mi * 16 + (lane >> 2);
                const int kq = ks * 16 + (lane & 3) * 2;
                const float* p = Xs + kq * XPITCH + tq;
                split_pair(p[0],              p[XPITCH],
                           ar0[mi][ks][0], ar1[mi][ks][0]);
                split_pair(p[8],              p[XPITCH + 8],
                           ar0[mi][ks][1], ar1[mi][ks][1]);
                split_pair(p[8 * XPITCH],     p[9 * XPITCH],
                           ar0[mi][ks][2], ar1[mi][ks][2]);
                split_pair(p[8 * XPITCH + 8], p[9 * XPITCH + 8],
                           ar0[mi][ks][3], ar1[mi][ks][3]);
            }
        }

        // ---- MMA: main fp32-acc, corrections fp16-acc ----
        #pragma unroll
        for (int ks = 0; ks < 2; ks++) {
            const int col = ks * 16 + (lane >> 4) * 8;
            uint32_t br0[2][4], br1[2][4];
            #pragma unroll
            for (int nb = 0; nb < 2; nb++) {
                int row = nw + nb * 16 + (lane & 15);
                ldsm4(bbase + (row * 40 + col) * 2,
                      br0[nb][0], br0[nb][1], br0[nb][2], br0[nb][3]);
                ldsm4(bbase + 5120 + (row * 40 + col) * 2,
                      br1[nb][0], br1[nb][1], br1[nb][2], br1[nb][3]);
            }
            #pragma unroll
            for (int mi = 0; mi < 2; mi++)
                #pragma unroll
                for (int nf = 0; nf < 4; nf++) {
                    int nb = nf >> 1, hh = nf & 1;
                    mma16816(acc[mi][nf],  ar0[mi][ks], br0[nb][hh], br0[nb][hh + 2]);
                    mma16816h(accc[mi][nf], ar0[mi][ks], br1[nb][hh], br1[nb][hh + 2]);
                    mma16816h(accc[mi][nf], ar1[mi][ks], br0[nb][hh], br0[nb][hh + 2]);
                }
        }
    }

    // epilogue: main + corrections;  frag map m = lane/4 (+8), n = 2*(lane%4) (+1)
    #pragma unroll
    for (int mi = 0; mi < 2; mi++) {
        int row = mt * 128 + mw + mi * 16 + (lane >> 2);
        #pragma unroll
        for (int nf = 0; nf < 4; nf++) {
            int col = n0 + nw + nf * 8 + ((lane & 3) << 1);
            float2 c01 = __half22float2(*(__half2*)&accc[mi][nf][0]);
            float2 c23 = __half22float2(*(__half2*)&accc[mi][nf][1]);
            *(float2*)(g_xw + (size_t)row * 512 + col) =
                make_float2(acc[mi][nf][0] + c01.x, acc[mi][nf][1] + c01.y);
            *(float2*)(g_xw + (size_t)(row + 8) * 512 + col) =
                make_float2(acc[mi][nf][2] + c23.x, acc[mi][nf][3] + c23.y);
        }
    }
}

// ---------------------------------------------------------------- recurrence ---
// v2 (proven 62us): 2-buffer cp.async staging.
__global__ __launch_bounds__(128) void recur_kernel(
    const float* __restrict__ bias, float* __restrict__ out)
{
    extern __shared__ float dyn[];
    float* smin = dyn;                               // [2][32*128]
    float (*buf)[33] = (float(*)[33])(dyn + 8192);   // [128][33]

    const int b  = blockIdx.x >> 2;
    const int h0 = (blockIdx.x & 3) * 128;
    const int h  = h0 + threadIdx.x;
    const int tid = threadIdx.x;

    const float bb = bias[h];
    float hs = 0.0f, y = 0.0f;

    const float* gx = g_xw + ((size_t)b * 512) * 512 + h0;
    float*       po = out + ((size_t)b * 512 + h0) * 512;

    const uint32_t smin_u = smem_u32(smin);
    const int lrow = tid >> 2;
    const int lq   = (tid & 3) * 32;

    #define RLOAD(tc0, bsel) do {                                             \
        const float* _src = gx + (size_t)((tc0) + lrow) * 512 + lq;           \
        uint32_t _dst = smin_u + (((bsel) * 4096 + lrow * 128 + lq) * 4);     \
        cp16(_dst,      _src);      cp16(_dst + 16, _src + 4);                \
        cp16(_dst + 32, _src + 8);  cp16(_dst + 48, _src + 12);               \
        cp16(_dst + 64, _src + 16); cp16(_dst + 80, _src + 20);               \
        cp16(_dst + 96, _src + 24); cp16(_dst + 112, _src + 28);              \
    } while (0)

    RLOAD(0, 0);
    asm volatile("cp.async.commit_group;" ::: "memory");

    for (int tc = 0; tc < 16; tc++) {
        if (tc < 15) {
            RLOAD((tc + 1) * 32, (tc + 1) & 1);
            asm volatile("cp.async.commit_group;" ::: "memory");
            asm volatile("cp.async.wait_group 1;" ::: "memory");
        } else {
            asm volatile("cp.async.wait_group 0;" ::: "memory");
        }
        __syncthreads();

        const float* cs = smin + (tc & 1) * 4096;
        #pragma unroll
        for (int j = 0; j < 32; j++) {
            float v = cs[j * 128 + tid];
            hs = fmaxf(v + 0.8f * hs * (1.0f - y), 0.0f);
            y  = (hs + bb > 0.0f) ? 1.0f : 0.0f;
            buf[tid][j] = y;
        }
        __syncthreads();
        const int r = tid >> 5;
        const int c = tid & 31;
        #pragma unroll
        for (int rr = 0; rr < 128; rr += 4)
            po[(size_t)(rr + r) * 512 + tc * 32 + c] = buf[rr + r][c];
        __syncthreads();
    }
}

// ------------------------------------------------------------------- launch ---
extern "C" void kernel_launch(void* const* d_in, const int* in_sizes, int n_in,
                              void* d_out, int out_size)
{
    const float* x = (const float*)d_in[0];   // (128, 512, 512)
    const float* W = (const float*)d_in[1];   // (512, 512)
    const float* b = (const float*)d_in[2];   // (1, 512)
    float* out = (float*)d_out;               // (128, 512, 512) float32

    cudaFuncSetAttribute(gemm_fc,
                         cudaFuncAttributeMaxDynamicSharedMemorySize, 4 * STG);
    cudaFuncSetAttribute(recur_kernel,
                         cudaFuncAttributeMaxDynamicSharedMemorySize, 49664);

    convert_w_kernel<<<dim3(8, 8), 256>>>(W);
    gemm_fc<<<dim3(8, 512), 256, 4 * STG>>>(x);
    recur_kernel<<<512, 128, 49664>>>(b, out);
}

// round 14
// speedup vs baseline: 2.3436x; 2.2671x over previous
#include <cuda_runtime.h>
#include <cuda_fp16.h>
#include <stdint.h>

// SNU on GB300 (base sm_103 ISA — mma.sync HMMA path):
//   out[b,h,t] = spike recurrence over xw[t,b,h] = sum_i x[b,i,t]*W[i,h]
//   B=128, I=512, H=512, T=512, DECAY=0.8
//
// v8 — algebraic collapse:  h_t = relu(...) >= 0, y_t = (h_t + bias > 0).
// If bias[h] > 0 then y == 1 for ALL t (exact, fp-safe: h>=0, b>0 => h+b>0).
// So the GEMM + recurrence are only needed for the ~16% of h-columns with
// bias <= 0 (nh ~ 81 of 512).  Structure:
//   scan_bias          -> compact hidx[] of columns with !(bias>0), g_nh
//   convert_w_compact  -> fp16 split pair of only those W columns (padded 0)
//   fill_ones          -> out rows with bias>0 := 1.0f
//   gemm_fc            -> round-13 proven body; n-tiles with n0>=nh exit
//   recur_kernel       -> round-8 proven v2 body over compacted cols, rows
//                         routed via hidx; j-tiles beyond nh exit

typedef unsigned long long ull;

__device__ float  g_xw[33554432];               // 65536 x 512 fp32 (compacted cols)
__device__ __half g_b0[262144], g_b1[262144];   // 512 x 512 fp16 splits (compacted)
__device__ int    g_nh;                         // # columns with !(bias>0)
__device__ int    g_hidx[512];                  // compacted j -> h

// ---------------------------------------------------------------- helpers ---
__device__ __forceinline__ uint32_t smem_u32(const void* p) {
    uint32_t a;
    asm("{ .reg .u64 t; cvta.to.shared.u64 t, %1; cvt.u32.u64 %0, t; }"
        : "=r"(a) : "l"(p));
    return a;
}
__device__ __forceinline__ void cp16(uint32_t dst, const void* src) {
    asm volatile("cp.async.cg.shared.global [%0], [%1], 16;"
                 :: "r"(dst), "l"(src) : "memory");
}
__device__ __forceinline__ void ldsm4(uint32_t a, uint32_t& r0, uint32_t& r1,
                                      uint32_t& r2, uint32_t& r3) {
    asm volatile("ldmatrix.sync.aligned.m8n8.x4.shared.b16 {%0,%1,%2,%3}, [%4];"
                 : "=r"(r0), "=r"(r1), "=r"(r2), "=r"(r3) : "r"(a));
}
__device__ __forceinline__ void mma16816(float* d, const uint32_t* a,
                                         uint32_t b0, uint32_t b1) {
    asm volatile(
        "mma.sync.aligned.m16n8k16.row.col.f32.f16.f16.f32 "
        "{%0,%1,%2,%3}, {%4,%5,%6,%7}, {%8,%9}, {%0,%1,%2,%3};"
        : "+f"(d[0]), "+f"(d[1]), "+f"(d[2]), "+f"(d[3])
        : "r"(a[0]), "r"(a[1]), "r"(a[2]), "r"(a[3]), "r"(b0), "r"(b1));
}
__device__ __forceinline__ void mma16816h(uint32_t* d, const uint32_t* a,
                                          uint32_t b0, uint32_t b1) {
    asm volatile(
        "mma.sync.aligned.m16n8k16.row.col.f16.f16.f16.f16 "
        "{%0,%1}, {%2,%3,%4,%5}, {%6,%7}, {%0,%1};"
        : "+r"(d[0]), "+r"(d[1])
        : "r"(a[0]), "r"(a[1]), "r"(a[2]), "r"(a[3]), "r"(b0), "r"(b1));
}
__device__ __forceinline__ void split_pair(float ve, float vo,
                                           uint32_t& r0, uint32_t& r1) {
    __half2 h = __floats2half2_rn(ve, vo);
    float2  w = __half22float2(h);
    __half2 g = __floats2half2_rn(ve - w.x, vo - w.y);
    r0 = *(uint32_t*)&h;
    r1 = *(uint32_t*)&g;
}

// ------------------------------------------------------------- scan_bias ---
__global__ void scan_bias(const float* __restrict__ bias) {
    int h = threadIdx.x;                      // 512 threads
    bool p = !(bias[h] > 0.0f);               // serial lane predicate (exact)
    unsigned m = __ballot_sync(0xffffffffu, p);
    int lane = h & 31, wid = h >> 5;
    __shared__ int wcnt[16], woff[16];
    if (lane == 0) wcnt[wid] = __popc(m);
    __syncthreads();
    if (h == 0) {
        int s = 0;
        for (int w = 0; w < 16; w++) { woff[w] = s; s += wcnt[w]; }
        g_nh = s;
    }
    __syncthreads();
    if (p) g_hidx[woff[wid] + __popc(m & ((1u << lane) - 1u))] = h;
}

// ----------------------------------------------------- convert_w_compact ---
// One CTA per compacted row j: gather W[:, hidx[j]] and fp16-split it.
__global__ __launch_bounds__(128) void convert_w_compact(const float* __restrict__ W) {
    const int j = blockIdx.x;                 // 0..511
    const int nh = g_nh;
    const int tid = threadIdx.x;
    if (j < nh) {
        const int h = g_hidx[j];
        for (int i = tid; i < 512; i += 128) {
            float v = W[(size_t)i * 512 + h];
            __half h0 = __float2half_rn(v);
            g_b0[j * 512 + i] = h0;
            g_b1[j * 512 + i] = __float2half_rn(v - __half2float(h0));
        }
    } else {
        for (int i = tid; i < 512; i += 128) {
            g_b0[j * 512 + i] = __ushort_as_half(0);
            g_b1[j * 512 + i] = __ushort_as_half(0);
        }
    }
}

// ------------------------------------------------------------- fill_ones ---
// out rows with bias>0 are identically 1.0 (exact).  Warp per (b,h) row.
__global__ __launch_bounds__(256) void fill_ones(const float* __restrict__ bias,
                                                 float* __restrict__ out) {
    const int row  = blockIdx.x * 8 + (threadIdx.x >> 5);   // b*512 + h
    const int lane = threadIdx.x & 31;
    if (bias[row & 511] > 0.0f) {
        float4 one = make_float4(1.f, 1.f, 1.f, 1.f);
        float4* p = (float4*)(out + (size_t)row * 512);
        #pragma unroll
        for (int q = 0; q < 4; q++) p[q * 32 + lane] = one;
    }
}

// ------------------------------------------------ GEMM w/ fused A-convert ---
// Round-13 proven body; n-tiles beyond the compacted column count exit.
#define STG    27136
#define XPITCH 132

__global__ __launch_bounds__(256, 2) void gemm_fc(const float* __restrict__ x) {
    const int n0 = blockIdx.x * 64;
    if (n0 >= g_nh) return;                   // compacted-N early exit

    extern __shared__ char smraw[];
    const uint32_t smb = smem_u32(smraw);

    const int tid  = threadIdx.x;
    const int mt   = blockIdx.y;              // m-tile 0..511
    const int b    = mt >> 2;
    const int t0   = (mt & 3) * 128;
    const int wid  = tid >> 5, lane = tid & 31;
    const int mw   = (wid >> 1) * 32;
    const int nw   = (wid & 1) * 32;

    const float* xb = x + (size_t)b * 262144 + t0;   // + k*512 + t

    float acc[2][4][4];
    uint32_t accc[2][4][2];
    #pragma unroll
    for (int i = 0; i < 2; i++)
        #pragma unroll
        for (int j = 0; j < 4; j++) {
            #pragma unroll
            for (int q = 0; q < 4; q++) acc[i][j][q] = 0.0f;
            accc[i][j][0] = 0u; accc[i][j][1] = 0u;
        }

    #define LOAD_CHUNK(c, slot) do {                                          \
        int _k0 = (c) << 5;                                                   \
        uint32_t _sb = smb + (slot) * STG;                                    \
        _Pragma("unroll")                                                     \
        for (int _q = 0; _q < 4; _q++) {                                      \
            int _e = tid + 256 * _q;                                          \
            int _r = _e >> 5, _c = _e & 31;                                   \
            cp16(_sb + _r * (XPITCH * 4) + _c * 16,                           \
                 xb + (size_t)(_k0 + _r) * 512 + _c * 4);                     \
        }                                                                     \
        {                                                                     \
            int _r = tid >> 2, _c4 = tid & 3;                                 \
            cp16(_sb + 16896 + _r * 80 + _c4 * 16,                            \
                 g_b0 + (size_t)(n0 + _r) * 512 + _k0 + _c4 * 8);             \
            cp16(_sb + 22016 + _r * 80 + _c4 * 16,                            \
                 g_b1 + (size_t)(n0 + _r) * 512 + _k0 + _c4 * 8);             \
        }                                                                     \
    } while (0)

    LOAD_CHUNK(0, 0); asm volatile("cp.async.commit_group;" ::: "memory");
    LOAD_CHUNK(1, 1); asm volatile("cp.async.commit_group;" ::: "memory");
    LOAD_CHUNK(2, 2); asm volatile("cp.async.commit_group;" ::: "memory");

    for (int i = 0; i < 16; i++) {
        asm volatile("cp.async.wait_group 2;" ::: "memory");
        __syncthreads();
        if (i + 3 < 16) LOAD_CHUNK(i + 3, (i + 3) & 3);
        asm volatile("cp.async.commit_group;" ::: "memory");

        const int slot = i & 3;
        const float* Xs = (const float*)(smraw + slot * STG);
        const uint32_t bbase = smb + slot * STG + 16896;

        uint32_t ar0[2][2][4], ar1[2][2][4];
        #pragma unroll
        for (int mi = 0; mi < 2; mi++) {
            #pragma unroll
            for (int ks = 0; ks < 2; ks++) {
                const int tq = mw + mi * 16 + (lane >> 2);
                const int kq = ks * 16 + (lane & 3) * 2;
                const float* p = Xs + kq * XPITCH + tq;
                split_pair(p[0],              p[XPITCH],
                           ar0[mi][ks][0], ar1[mi][ks][0]);
                split_pair(p[8],              p[XPITCH + 8],
                           ar0[mi][ks][1], ar1[mi][ks][1]);
                split_pair(p[8 * XPITCH],     p[9 * XPITCH],
                           ar0[mi][ks][2], ar1[mi][ks][2]);
                split_pair(p[8 * XPITCH + 8], p[9 * XPITCH + 8],
                           ar0[mi][ks][3], ar1[mi][ks][3]);
            }
        }

        #pragma unroll
        for (int ks = 0; ks < 2; ks++) {
            const int col = ks * 16 + (lane >> 4) * 8;
            uint32_t br0[2][4], br1[2][4];
            #pragma unroll
            for (int nb = 0; nb < 2; nb++) {
                int row = nw + nb * 16 + (lane & 15);
                ldsm4(bbase + (row * 40 + col) * 2,
                      br0[nb][0], br0[nb][1], br0[nb][2], br0[nb][3]);
                ldsm4(bbase + 5120 + (row * 40 + col) * 2,
                      br1[nb][0], br1[nb][1], br1[nb][2], br1[nb][3]);
            }
            #pragma unroll
            for (int mi = 0; mi < 2; mi++)
                #pragma unroll
                for (int nf = 0; nf < 4; nf++) {
                    int nb = nf >> 1, hh = nf & 1;
                    mma16816(acc[mi][nf],   ar0[mi][ks], br0[nb][hh], br0[nb][hh + 2]);
                    mma16816h(accc[mi][nf], ar0[mi][ks], br1[nb][hh], br1[nb][hh + 2]);
                    mma16816h(accc[mi][nf], ar1[mi][ks], br0[nb][hh], br0[nb][hh + 2]);
                }
        }
    }

    #pragma unroll
    for (int mi = 0; mi < 2; mi++) {
        int row = mt * 128 + mw + mi * 16 + (lane >> 2);
        #pragma unroll
        for (int nf = 0; nf < 4; nf++) {
            int col = n0 + nw + nf * 8 + ((lane & 3) << 1);
            float2 c01 = __half22float2(*(__half2*)&accc[mi][nf][0]);
            float2 c23 = __half22float2(*(__half2*)&accc[mi][nf][1]);
            *(float2*)(g_xw + (size_t)row * 512 + col) =
                make_float2(acc[mi][nf][0] + c01.x, acc[mi][nf][1] + c01.y);
            *(float2*)(g_xw + (size_t)(row + 8) * 512 + col) =
                make_float2(acc[mi][nf][2] + c23.x, acc[mi][nf][3] + c23.y);
        }
    }
}

// ---------------------------------------------------------------- recurrence ---
// v2 body over compacted columns; output rows routed through g_hidx.
__global__ __launch_bounds__(128) void recur_kernel(
    const float* __restrict__ bias, float* __restrict__ out)
{
    const int nh = g_nh;
    const int b  = blockIdx.x >> 2;
    const int jt = blockIdx.x & 3;
    if (jt * 128 >= nh) return;               // compacted-j early exit

    extern __shared__ float dyn[];
    float* smin = dyn;                               // [2][32*128]
    float (*buf)[33] = (float(*)[33])(dyn + 8192);   // [128][33]
    __shared__ int sh_h[128];

    const int tid = threadIdx.x;
    const int j   = jt * 128 + tid;
    const bool valid = j < nh;
    const int h = valid ? g_hidx[j] : 0;
    sh_h[tid] = h;
    const float bb = valid ? bias[h] : 0.0f;

    float hs = 0.0f, y = 0.0f;

    const float* gx = g_xw + (size_t)b * 262144 + jt * 128;  // + t*512 + tid
    float*       po = out + (size_t)b * 262144;              // row via sh_h

    const uint32_t smin_u = smem_u32(smin);
    const int lrow = tid >> 2;
    const int lq   = (tid & 3) * 32;

    #define RLOAD(tc0, bsel) do {                                             \
        const float* _src = gx + (size_t)((tc0) + lrow) * 512 + lq;           \
        uint32_t _dst = smin_u + (((bsel) * 4096 + lrow * 128 + lq) * 4);     \
        cp16(_dst,      _src);      cp16(_dst + 16, _src + 4);                \
        cp16(_dst + 32, _src + 8);  cp16(_dst + 48, _src + 12);               \
        cp16(_dst + 64, _src + 16); cp16(_dst + 80, _src + 20);               \
        cp16(_dst + 96, _src + 24); cp16(_dst + 112, _src + 28);              \
    } while (0)

    RLOAD(0, 0);
    asm volatile("cp.async.commit_group;" ::: "memory");

    for (int tc = 0; tc < 16; tc++) {
        if (tc < 15) {
            RLOAD((tc + 1) * 32, (tc + 1) & 1);
            asm volatile("cp.async.commit_group;" ::: "memory");
            asm volatile("cp.async.wait_group 1;" ::: "memory");
        } else {
            asm volatile("cp.async.wait_group 0;" ::: "memory");
        }
        __syncthreads();

        const float* cs = smin + (tc & 1) * 4096;
        #pragma unroll
        for (int jj = 0; jj < 32; jj++) {
            float v = cs[jj * 128 + tid];
            hs = fmaxf(v + 0.8f * hs * (1.0f - y), 0.0f);
            y  = (hs + bb > 0.0f) ? 1.0f : 0.0f;
            buf[tid][jj] = y;
        }
        __syncthreads();
        const int r = tid >> 5;
        const int c = tid & 31;
        #pragma unroll
        for (int rr = 0; rr < 128; rr += 4) {
            int jrow = rr + r;
            if (jt * 128 + jrow < nh)
                po[(size_t)sh_h[jrow] * 512 + tc * 32 + c] = buf[jrow][c];
        }
        __syncthreads();
    }
}

// ------------------------------------------------------------------- launch ---
extern "C" void kernel_launch(void* const* d_in, const int* in_sizes, int n_in,
                              void* d_out, int out_size)
{
    const float* x = (const float*)d_in[0];   // (128, 512, 512)
    const float* W = (const float*)d_in[1];   // (512, 512)
    const float* b = (const float*)d_in[2];   // (1, 512)
    float* out = (float*)d_out;               // (128, 512, 512) float32

    cudaFuncSetAttribute(gemm_fc,
                         cudaFuncAttributeMaxDynamicSharedMemorySize, 4 * STG);
    cudaFuncSetAttribute(recur_kernel,
                         cudaFuncAttributeMaxDynamicSharedMemorySize, 49664);

    scan_bias<<<1, 512>>>(b);
    convert_w_compact<<<512, 128>>>(W);
    fill_ones<<<8192, 256>>>(b, out);
    gemm_fc<<<dim3(8, 512), 256, 4 * STG>>>(x);
    recur_kernel<<<512, 128, 49664>>>(b, out);
}

// round 15
// speedup vs baseline: 2.8241x; 1.2050x over previous
#include <cuda_runtime.h>
#include <cuda_fp16.h>
#include <stdint.h>

// SNU on GB300 (base sm_103 ISA — mma.sync HMMA path):
//   out[b,h,t] = spike recurrence over xw[t,b,h] = sum_i x[b,i,t]*W[i,h]
//   B=128, I=512, H=512, T=512, DECAY=0.8
//
// v9 — algebraic collapse (round 14) + single fused main kernel:
//   bias>0  => y == 1 for all t (exact).  Only nh ~ 81 columns need compute.
//   scan_bias         -> hidx[] compaction, g_nh, zero per-batch flags
//   convert_w_compact -> fp16 split of only the needed W columns
//   fused (grid 4608 = 4096 gemm-slots + 512 recur):
//     bid<4096: mt=bid>>3, n=bid&7.  n0<nh  -> round-13 GEMM body + flag.
//               n>=2 -> 22-row slice of the out:=1.0 fill (interleaved bids
//               stream the fill under the GEMM's idle DRAM).
//     bid>=4096: recur CTA; spins on its batch's producer flags, then runs
//               the proven v2 staged recurrence routed through hidx.

typedef unsigned long long ull;

__device__ float  g_xw[33554432];               // 65536 x 512 fp32 (compacted cols)
__device__ __half g_b0[262144], g_b1[262144];   // 512 x 512 fp16 splits (compacted)
__device__ int    g_nh;                         // # columns with !(bias>0)
__device__ int    g_hidx[512];                  // compacted j -> h
__device__ int    g_bflag[128];                 // per-batch producer counters

// ---------------------------------------------------------------- helpers ---
__device__ __forceinline__ uint32_t smem_u32(const void* p) {
    uint32_t a;
    asm("{ .reg .u64 t; cvta.to.shared.u64 t, %1; cvt.u32.u64 %0, t; }"
        : "=r"(a) : "l"(p));
    return a;
}
__device__ __forceinline__ void cp16(uint32_t dst, const void* src) {
    asm volatile("cp.async.cg.shared.global [%0], [%1], 16;"
                 :: "r"(dst), "l"(src) : "memory");
}
__device__ __forceinline__ void ldsm4(uint32_t a, uint32_t& r0, uint32_t& r1,
                                      uint32_t& r2, uint32_t& r3) {
    asm volatile("ldmatrix.sync.aligned.m8n8.x4.shared.b16 {%0,%1,%2,%3}, [%4];"
                 : "=r"(r0), "=r"(r1), "=r"(r2), "=r"(r3) : "r"(a));
}
__device__ __forceinline__ void mma16816(float* d, const uint32_t* a,
                                         uint32_t b0, uint32_t b1) {
    asm volatile(
        "mma.sync.aligned.m16n8k16.row.col.f32.f16.f16.f32 "
        "{%0,%1,%2,%3}, {%4,%5,%6,%7}, {%8,%9}, {%0,%1,%2,%3};"
        : "+f"(d[0]), "+f"(d[1]), "+f"(d[2]), "+f"(d[3])
        : "r"(a[0]), "r"(a[1]), "r"(a[2]), "r"(a[3]), "r"(b0), "r"(b1));
}
__device__ __forceinline__ void mma16816h(uint32_t* d, const uint32_t* a,
                                          uint32_t b0, uint32_t b1) {
    asm volatile(
        "mma.sync.aligned.m16n8k16.row.col.f16.f16.f16.f16 "
        "{%0,%1}, {%2,%3,%4,%5}, {%6,%7}, {%0,%1};"
        : "+r"(d[0]), "+r"(d[1])
        : "r"(a[0]), "r"(a[1]), "r"(a[2]), "r"(a[3]), "r"(b0), "r"(b1));
}
__device__ __forceinline__ void split_pair(float ve, float vo,
                                           uint32_t& r0, uint32_t& r1) {
    __half2 h = __floats2half2_rn(ve, vo);
    float2  w = __half22float2(h);
    __half2 g = __floats2half2_rn(ve - w.x, vo - w.y);
    r0 = *(uint32_t*)&h;
    r1 = *(uint32_t*)&g;
}

// ------------------------------------------------------------- scan_bias ---
__global__ void scan_bias(const float* __restrict__ bias) {
    int h = threadIdx.x;                      // 512 threads
    if (h < 128) g_bflag[h] = 0;              // reset producer flags
    bool p = !(bias[h] > 0.0f);
    unsigned m = __ballot_sync(0xffffffffu, p);
    int lane = h & 31, wid = h >> 5;
    __shared__ int wcnt[16], woff[16];
    if (lane == 0) wcnt[wid] = __popc(m);
    __syncthreads();
    if (h == 0) {
        int s = 0;
        for (int w = 0; w < 16; w++) { woff[w] = s; s += wcnt[w]; }
        g_nh = s;
    }
    __syncthreads();
    if (p) g_hidx[woff[wid] + __popc(m & ((1u << lane) - 1u))] = h;
}

// ----------------------------------------------------- convert_w_compact ---
__global__ __launch_bounds__(128) void convert_w_compact(const float* __restrict__ W) {
    const int j = blockIdx.x;                 // 0..511
    const int nh = g_nh;
    const int tid = threadIdx.x;
    if (j < nh) {
        const int h = g_hidx[j];
        for (int i = tid; i < 512; i += 128) {
            float v = W[(size_t)i * 512 + h];
            __half h0 = __float2half_rn(v);
            g_b0[j * 512 + i] = h0;
            g_b1[j * 512 + i] = __float2half_rn(v - __half2float(h0));
        }
    } else {
        for (int i = tid; i < 512; i += 128) {
            g_b0[j * 512 + i] = __ushort_as_half(0);
            g_b1[j * 512 + i] = __ushort_as_half(0);
        }
    }
}

// ----------------------------------------------------------- fused kernel ---
#define STG    27136
#define XPITCH 132
#define NGEMM  4096

__global__ __launch_bounds__(256, 2) void fused_kernel(
    const float* __restrict__ x, const float* __restrict__ bias,
    float* __restrict__ out)
{
    extern __shared__ char smraw[];
    const uint32_t smb = smem_u32(smraw);
    const int tid = threadIdx.x;
    const int nh  = g_nh;

    if (blockIdx.x < NGEMM) {
        const int bid   = blockIdx.x;
        const int mt    = bid >> 3;           // m-tile 0..511 (batch-major)
        const int n_idx = bid & 7;
        const int n0    = n_idx * 64;

        if (n0 < nh) {
            // ================= GEMM CTA (round-13 proven body) ============
            const int b    = mt >> 2;
            const int t0   = (mt & 3) * 128;
            const int wid  = tid >> 5, lane = tid & 31;
            const int mw   = (wid >> 1) * 32;
            const int nw   = (wid & 1) * 32;

            const float* xb = x + (size_t)b * 262144 + t0;

            float acc[2][4][4];
            uint32_t accc[2][4][2];
            #pragma unroll
            for (int i = 0; i < 2; i++)
                #pragma unroll
                for (int j = 0; j < 4; j++) {
                    #pragma unroll
                    for (int q = 0; q < 4; q++) acc[i][j][q] = 0.0f;
                    accc[i][j][0] = 0u; accc[i][j][1] = 0u;
                }

            #define LOAD_CHUNK(c, slot) do {                                  \
                int _k0 = (c) << 5;                                           \
                uint32_t _sb = smb + (slot) * STG;                            \
                _Pragma("unroll")                                             \
                for (int _q = 0; _q < 4; _q++) {                              \
                    int _e = tid + 256 * _q;                                  \
                    int _r = _e >> 5, _c = _e & 31;                           \
                    cp16(_sb + _r * (XPITCH * 4) + _c * 16,                   \
                         xb + (size_t)(_k0 + _r) * 512 + _c * 4);             \
                }                                                             \
                {                                                             \
                    int _r = tid >> 2, _c4 = tid & 3;                         \
                    cp16(_sb + 16896 + _r * 80 + _c4 * 16,                    \
                         g_b0 + (size_t)(n0 + _r) * 512 + _k0 + _c4 * 8);     \
                    cp16(_sb + 22016 + _r * 80 + _c4 * 16,                    \
                         g_b1 + (size_t)(n0 + _r) * 512 + _k0 + _c4 * 8);     \
                }                                                             \
            } while (0)

            LOAD_CHUNK(0, 0); asm volatile("cp.async.commit_group;" ::: "memory");
            LOAD_CHUNK(1, 1); asm volatile("cp.async.commit_group;" ::: "memory");
            LOAD_CHUNK(2, 2); asm volatile("cp.async.commit_group;" ::: "memory");

            for (int i = 0; i < 16; i++) {
                asm volatile("cp.async.wait_group 2;" ::: "memory");
                __syncthreads();
                if (i + 3 < 16) LOAD_CHUNK(i + 3, (i + 3) & 3);
                asm volatile("cp.async.commit_group;" ::: "memory");

                const int slot = i & 3;
                const float* Xs = (const float*)(smraw + slot * STG);
                const uint32_t bbase = smb + slot * STG + 16896;

                uint32_t ar0[2][2][4], ar1[2][2][4];
                #pragma unroll
                for (int mi = 0; mi < 2; mi++) {
                    #pragma unroll
                    for (int ks = 0; ks < 2; ks++) {
                        const int tq = mw + mi * 16 + (lane >> 2);
                        const int kq = ks * 16 + (lane & 3) * 2;
                        const float* p = Xs + kq * XPITCH + tq;
                        split_pair(p[0],              p[XPITCH],
                                   ar0[mi][ks][0], ar1[mi][ks][0]);
                        split_pair(p[8],              p[XPITCH + 8],
                                   ar0[mi][ks][1], ar1[mi][ks][1]);
                        split_pair(p[8 * XPITCH],     p[9 * XPITCH],
                                   ar0[mi][ks][2], ar1[mi][ks][2]);
                        split_pair(p[8 * XPITCH + 8], p[9 * XPITCH + 8],
                                   ar0[mi][ks][3], ar1[mi][ks][3]);
                    }
                }

                #pragma unroll
                for (int ks = 0; ks < 2; ks++) {
                    const int col = ks * 16 + (lane >> 4) * 8;
                    uint32_t br0[2][4], br1[2][4];
                    #pragma unroll
                    for (int nb = 0; nb < 2; nb++) {
                        int row = nw + nb * 16 + (lane & 15);
                        ldsm4(bbase + (row * 40 + col) * 2,
                              br0[nb][0], br0[nb][1], br0[nb][2], br0[nb][3]);
                        ldsm4(bbase + 5120 + (row * 40 + col) * 2,
                              br1[nb][0], br1[nb][1], br1[nb][2], br1[nb][3]);
                    }
                    #pragma unroll
                    for (int mi = 0; mi < 2; mi++)
                        #pragma unroll
                        for (int nf = 0; nf < 4; nf++) {
                            int nb = nf >> 1, hh = nf & 1;
                            mma16816(acc[mi][nf],   ar0[mi][ks], br0[nb][hh], br0[nb][hh + 2]);
                            mma16816h(accc[mi][nf], ar0[mi][ks], br1[nb][hh], br1[nb][hh + 2]);
                            mma16816h(accc[mi][nf], ar1[mi][ks], br0[nb][hh], br0[nb][hh + 2]);
                        }
                }
            }

            #pragma unroll
            for (int mi = 0; mi < 2; mi++) {
                int row = mt * 128 + mw + mi * 16 + (lane >> 2);
                #pragma unroll
                for (int nf = 0; nf < 4; nf++) {
                    int col = n0 + nw + nf * 8 + ((lane & 3) << 1);
                    float2 c01 = __half22float2(*(__half2*)&accc[mi][nf][0]);
                    float2 c23 = __half22float2(*(__half2*)&accc[mi][nf][1]);
                    *(float2*)(g_xw + (size_t)row * 512 + col) =
                        make_float2(acc[mi][nf][0] + c01.x, acc[mi][nf][1] + c01.y);
                    *(float2*)(g_xw + (size_t)(row + 8) * 512 + col) =
                        make_float2(acc[mi][nf][2] + c23.x, acc[mi][nf][3] + c23.y);
                }
            }

            __threadfence();
            __syncthreads();
            if (tid == 0) atomicAdd(&g_bflag[mt >> 2], 1);
        }

        if (n_idx >= 2) {
            // ================= fill duty: 22 rows of out := 1.0 ===========
            const int fid = mt * 6 + (n_idx - 2);          // 0..3071
            const int r0 = fid * 22;
            const int r1 = (r0 + 22 < 65536) ? r0 + 22 : 65536;
            const float4 one = make_float4(1.f, 1.f, 1.f, 1.f);
            for (int rr = r0; rr < r1; rr += 2) {
                int r = rr + (tid >> 7);
                if (r < r1 && bias[r & 511] > 0.0f)
                    ((float4*)(out + (size_t)r * 512))[tid & 127] = one;
            }
        }

    } else {
        // ===================== recur CTA (v2, 256-thread) =================
        const int rid = blockIdx.x - NGEMM;   // 0..511
        const int b   = rid >> 2;
        const int jt  = rid & 3;
        if (jt * 128 >= nh) return;

        const int nt = (nh + 63) >> 6;        // active n-tiles
        const int target = nt * 4;            // producers per batch
        if (tid == 0) {
            while (atomicAdd(&g_bflag[b], 0) < target) __nanosleep(100);
        }
        __syncthreads();
        __threadfence();

        float* smin = (float*)smraw;                          // [2][32*128]
        float (*buf)[33] = (float(*)[33])(smraw + 32768);     // [128][33]
        __shared__ int sh_h[128];

        const int j = jt * 128 + (tid & 127);
        const bool valid = j < nh;
        if (tid < 128) sh_h[tid] = valid ? g_hidx[j] : 0;
        float bb = 0.0f, hs = 0.0f, y = 0.0f;
        if (tid < 128 && valid) bb = bias[g_hidx[j]];

        const float* gx = g_xw + (size_t)b * 262144 + jt * 128;
        float*       po = out + (size_t)b * 262144;

        const uint32_t smin_u = smem_u32(smin);
        const int lrow = tid >> 3;            // 0..31
        const int lq   = (tid & 7) * 16;

        #define RLOAD(tc0, bsel) do {                                         \
            const float* _src = gx + (size_t)((tc0) + lrow) * 512 + lq;       \
            uint32_t _dst = smin_u + (((bsel) * 4096 + lrow * 128 + lq) * 4); \
            cp16(_dst,      _src);      cp16(_dst + 16, _src + 4);            \
            cp16(_dst + 32, _src + 8);  cp16(_dst + 48, _src + 12);           \
        } while (0)

        RLOAD(0, 0);
        asm volatile("cp.async.commit_group;" ::: "memory");

        for (int tc = 0; tc < 16; tc++) {
            if (tc < 15) {
                RLOAD((tc + 1) * 32, (tc + 1) & 1);
                asm volatile("cp.async.commit_group;" ::: "memory");
                asm volatile("cp.async.wait_group 1;" ::: "memory");
            } else {
                asm volatile("cp.async.wait_group 0;" ::: "memory");
            }
            __syncthreads();

            const float* cs = smin + (tc & 1) * 4096;
            if (tid < 128) {
                #pragma unroll
                for (int jj = 0; jj < 32; jj++) {
                    float v = cs[jj * 128 + tid];
                    hs = fmaxf(v + 0.8f * hs * (1.0f - y), 0.0f);
                    y  = (hs + bb > 0.0f) ? 1.0f : 0.0f;
                    buf[tid][jj] = y;
                }
            }
            __syncthreads();
            const int r = tid >> 5;           // 0..7
            const int c = tid & 31;
            #pragma unroll
            for (int rr = 0; rr < 128; rr += 8) {
                int jrow = rr + r;
                if (jt * 128 + jrow < nh)
                    po[(size_t)sh_h[jrow] * 512 + tc * 32 + c] = buf[jrow][c];
            }
            __syncthreads();
        }
    }
}

// ------------------------------------------------------------------- launch ---
extern "C" void kernel_launch(void* const* d_in, const int* in_sizes, int n_in,
                              void* d_out, int out_size)
{
    const float* x = (const float*)d_in[0];   // (128, 512, 512)
    const float* W = (const float*)d_in[1];   // (512, 512)
    const float* b = (const float*)d_in[2];   // (1, 512)
    float* out = (float*)d_out;               // (128, 512, 512) float32

    cudaFuncSetAttribute(fused_kernel,
                         cudaFuncAttributeMaxDynamicSharedMemorySize, 4 * STG);

    scan_bias<<<1, 512>>>(b);
    convert_w_compact<<<512, 128>>>(W);
    fused_kernel<<<NGEMM + 512, 256, 4 * STG>>>(x, b, out);
}